// round 17
// baseline (speedup 1.0000x reference)
#include <cuda_runtime.h>
#include <cuda_bf16.h>
#include <math.h>
#include <stdint.h>

#define BB   8
#define SSL  2048
#define DD   512
#define KF   256      // n_kernels
#define JJ   9
#define CC   4096
#define PADW 4

// ---------------- static device scratch (allocation-free rule) ----------------
__device__ __nv_bfloat16 g_xemb [(size_t)BB*SSL*DD];   // 16 MB
__device__ __nv_bfloat16 g_wtT  [(size_t)JJ*KF*DD];    // 2.25 MB [j][k][d]
__device__ __nv_bfloat16 g_Ubf  [(size_t)CC*KF];       // 2 MB
__device__ __nv_bfloat16 g_xf   [(size_t)BB*SSL*KF];   // 8 MB  [b][s][k]

// ---------------- PTX helpers (base-ISA only) ----------------
__device__ __forceinline__ uint32_t smem_u32(const void* p) {
    uint32_t a;
    asm("{ .reg .u64 t; cvta.to.shared.u64 t, %1; cvt.u32.u64 %0, t; }" : "=r"(a) : "l"(p));
    return a;
}
__device__ __forceinline__ void ldsm_x4(uint32_t& r0, uint32_t& r1, uint32_t& r2, uint32_t& r3,
                                        uint32_t addr) {
    asm volatile("ldmatrix.sync.aligned.m8n8.x4.shared.b16 {%0,%1,%2,%3}, [%4];"
                 : "=r"(r0), "=r"(r1), "=r"(r2), "=r"(r3) : "r"(addr));
}
__device__ __forceinline__ void ldsm_x4_t(uint32_t& r0, uint32_t& r1, uint32_t& r2, uint32_t& r3,
                                          uint32_t addr) {
    asm volatile("ldmatrix.sync.aligned.m8n8.x4.trans.shared.b16 {%0,%1,%2,%3}, [%4];"
                 : "=r"(r0), "=r"(r1), "=r"(r2), "=r"(r3) : "r"(addr));
}
__device__ __forceinline__ void mma_bf16(float* c, uint32_t a0, uint32_t a1, uint32_t a2,
                                         uint32_t a3, uint32_t b0, uint32_t b1) {
    asm volatile("mma.sync.aligned.m16n8k16.row.col.f32.bf16.bf16.f32 "
                 "{%0,%1,%2,%3}, {%4,%5,%6,%7}, {%8,%9}, {%0,%1,%2,%3};"
                 : "+f"(c[0]), "+f"(c[1]), "+f"(c[2]), "+f"(c[3])
                 : "r"(a0), "r"(a1), "r"(a2), "r"(a3), "r"(b0), "r"(b1));
}
__device__ __forceinline__ float htanh(float x) {
    float y; asm("tanh.approx.f32 %0, %1;" : "=f"(y) : "f"(x)); return y;
}
#define CPA(dst, src, sz) \
    asm volatile("cp.async.ca.shared.global [%0], [%1], 16, %2;" \
                 :: "r"(dst), "l"(src), "r"(sz) : "memory")
#define CP_COMMIT() asm volatile("cp.async.commit_group;" ::: "memory")
#define CP_WAIT1()  asm volatile("cp.async.wait_group 1;" ::: "memory")
#define CP_WAIT0()  asm volatile("cp.async.wait_group 0;" ::: "memory")

#define ASTR 40     // conv tiles: [rows][32] bf16 stride

// fast e^x on FMA pipe
__device__ __forceinline__ float fast_exp(float x) {
    float y = x * 1.44269504089f;
    float n = rintf(y);
    float f = y - n;
    float p = 0.0096180489f;
    p = fmaf(p, f, 0.0555041087f);
    p = fmaf(p, f, 0.2402265069f);
    p = fmaf(p, f, 0.6931471806f);
    p = fmaf(p, f, 1.0f);
    int ni = (int)n;
    if (ni < -126) ni = -126;
    if (ni >  127) ni =  127;
    return __int_as_float((ni + 127) << 23) * p;
}

// ---------------- prep kernels ----------------
__global__ void k_gather(const int* __restrict__ text, const float* __restrict__ table) {
    int idx = blockIdx.x * blockDim.x + threadIdx.x;
    const int total = BB * SSL * (DD / 4);
    if (idx >= total) return;
    int d4 = idx & (DD / 4 - 1);
    int bs = idx >> 7;
    int tok = text[bs];
    float4 v = reinterpret_cast<const float4*>(table)[(size_t)tok * (DD / 4) + d4];
    __nv_bfloat162 h0 = __floats2bfloat162_rn(v.x, v.y);
    __nv_bfloat162 h1 = __floats2bfloat162_rn(v.z, v.w);
    uint2 o = make_uint2(*(uint32_t*)&h0, *(uint32_t*)&h1);
    *reinterpret_cast<uint2*>(g_xemb + (size_t)bs * DD + d4 * 4) = o;
}
__global__ void k_wprep(const float* __restrict__ w) {
    int idx = blockIdx.x * blockDim.x + threadIdx.x;
    if (idx >= JJ * KF * DD) return;
    int d = idx % DD;
    int k = (idx / DD) % KF;
    int j = idx / (DD * KF);
    g_wtT[idx] = __float2bfloat16(w[((size_t)k * DD + d) * JJ + j]);
}
__global__ void k_uprep(const float* __restrict__ u) {
    int idx = blockIdx.x * blockDim.x + threadIdx.x;
    if (idx >= CC * KF) return;
    g_Ubf[idx] = __float2bfloat16(u[idx]);
}

// ---------------- 1) conv: halo-A implicit GEMM (unchanged from R16) ----------------
#define CONV_A_ROWS 136
#define CONV_A_STG  (CONV_A_ROWS * ASTR * 2)          // 10880
#define CONV_B_STG  (192 * ASTR * 2)                  // 15360

__global__ __launch_bounds__(256) void k_conv_mma(const float* __restrict__ convb) {
    extern __shared__ __align__(16) char dsm[];
    const uint32_t aA0 = smem_u32(dsm);
    const uint32_t aB0 = aA0 + 3 * CONV_A_STG;
    __shared__ float sbias[64];

    const int tid = threadIdx.x, wid = tid >> 5, lane = tid & 31;
    const int s0 = blockIdx.x * 128, k0 = blockIdx.y * 64, b = blockIdx.z;
    const int wm = (wid & 3) * 32, wn = (wid >> 2) * 32;
    if (tid < 64) sbias[tid] = convb[k0 + tid];

    float acc[2][4][4] = {};
    const int lrow = (lane & 7) + ((lane >> 3) & 1) * 8;
    const int lcol = ((lane >> 4) & 1) * 8;

    auto load_chunk = [&](int ch, int st) {
        const int dc = ch / 3, jg = ch % 3;
        const uint32_t aA = aA0 + st * CONV_A_STG;
        const uint32_t aB = aB0 + st * CONV_B_STG;
        for (int i = tid; i < 1312; i += 256) {
            if (i < 544) {
                int row = i >> 2, cs = i & 3;
                int g = s0 - PADW + row;
                unsigned ok = ((unsigned)g < SSL);
                const void* src = g_xemb + ((size_t)b * SSL + (ok ? g : 0)) * DD + dc * 32 + cs * 8;
                CPA(aA + (row * ASTR + cs * 8) * 2, src, ok ? 16u : 0u);
            } else {
                int idx = i - 544;
                int jl = idx >> 8;
                int rem = idx & 255;
                int row = rem >> 2, cs = rem & 3;
                int j = jg * 3 + jl;
                const void* src = g_wtT + ((size_t)j * KF + k0 + row) * DD + dc * 32 + cs * 8;
                CPA(aB + ((jl * 64 + row) * ASTR + cs * 8) * 2, src, 16u);
            }
        }
    };

    const int NC = (DD / 32) * 3;     // 48
    load_chunk(0, 0); CP_COMMIT();
    load_chunk(1, 1); CP_COMMIT();
    for (int ch = 0; ch < NC; ch++) {
        if (ch == NC - 1) CP_WAIT0(); else CP_WAIT1();
        __syncthreads();
        if (ch + 2 < NC) { load_chunk(ch + 2, (ch + 2) % 3); CP_COMMIT(); }
        const int st = ch % 3;
        const int jg = ch % 3;
        const uint32_t aA = aA0 + st * CONV_A_STG;
        const uint32_t aB = aB0 + st * CONV_B_STG;
        #pragma unroll
        for (int jl = 0; jl < 3; jl++) {
            const int j = jg * 3 + jl;
            #pragma unroll
            for (int ks = 0; ks < 2; ks++) {
                uint32_t a[2][4];
                #pragma unroll
                for (int mt = 0; mt < 2; mt++)
                    ldsm_x4(a[mt][0], a[mt][1], a[mt][2], a[mt][3],
                            aA + ((wm + mt * 16 + lrow + j) * ASTR + ks * 16 + lcol) * 2);
                #pragma unroll
                for (int nt = 0; nt < 2; nt++) {
                    uint32_t b0, b1, b2, b3;
                    ldsm_x4(b0, b1, b2, b3,
                            aB + ((jl * 64 + wn + nt * 16 + lrow) * ASTR + ks * 16 + lcol) * 2);
                    #pragma unroll
                    for (int mt = 0; mt < 2; mt++) {
                        mma_bf16(acc[mt][nt * 2 + 0], a[mt][0], a[mt][1], a[mt][2], a[mt][3], b0, b2);
                        mma_bf16(acc[mt][nt * 2 + 1], a[mt][0], a[mt][1], a[mt][2], a[mt][3], b1, b3);
                    }
                }
            }
        }
    }

    const int lr = lane >> 2, lc = (lane & 3) * 2;
    #pragma unroll
    for (int mt = 0; mt < 2; mt++)
        #pragma unroll
        for (int h = 0; h < 2; h++) {
            int s = s0 + wm + mt * 16 + lr + h * 8;
            __nv_bfloat16* orow = g_xf + ((size_t)b * SSL + s) * KF + k0;
            #pragma unroll
            for (int nt = 0; nt < 4; nt++) {
                int kc = wn + nt * 8 + lc;
                __nv_bfloat162 hh = __floats2bfloat162_rn(
                    htanh(acc[mt][nt][h * 2 + 0] + sbias[kc]),
                    htanh(acc[mt][nt][h * 2 + 1] + sbias[kc + 1]));
                *reinterpret_cast<uint32_t*>(orow + kc) = *(uint32_t*)&hh;
            }
        }
}

// ---------------- 2) FUSED attention: scores -> exp -> m -> y, one kernel ----------------
// Per CTA: 64 classes (c0), one batch b. Stream s in chunks of 128.
//   phase1: S[64c][128s] = U[64c][256kf] @ xf[128s][256kf]^T  (MMA, non-trans B)
//           alpha = exp(S) -> bf16 smem tile; l partials in regs
//   phase2: macc[64c][256k] += alpha[64c][128s] @ xf[128s][256k] (MMA, trans B)
//   epilogue: y[c] = sum_k fw[c][k] * macc[c][k]/l[c] + fb[c]
#define USTR  264                          // U smem stride (bf16)
#define XSTR  264                          // xf smem stride (bf16)
#define ALSTR 136                          // alpha smem stride (bf16)
#define U_BYTES   (64 * USTR * 2)          // 33792
#define XF_BYTES  (128 * XSTR * 2)         // 67584 per buffer
#define AL_BYTES  (64 * ALSTR * 2)         // 17408
#define SM_FUSED  (U_BYTES + 2 * XF_BYTES + AL_BYTES)   // 186368

__global__ __launch_bounds__(256) void k_fused(const float* __restrict__ fw,
                                               const float* __restrict__ fb,
                                               float* __restrict__ out) {
    extern __shared__ __align__(16) char dsm[];
    const uint32_t aU  = smem_u32(dsm);
    const uint32_t aX0 = aU + U_BYTES;
    const uint32_t aAL = aX0 + 2 * XF_BYTES;
    __shared__ float s_l[64];
    __shared__ float s_y[64];

    const int tid = threadIdx.x, w = tid >> 5, lane = tid & 31;
    const int c0 = blockIdx.x * 64, b = blockIdx.y;
    const int wcm = (w >> 2) * 32;         // c offset of this warp (phase1 + phase2)
    const int wsn = (w & 3) * 32;          // s offset (phase1)
    const int wkn = (w & 3) * 64;          // k offset (phase2)
    const int lrow = (lane & 7) + ((lane >> 3) & 1) * 8;
    const int lcol = ((lane >> 4) & 1) * 8;
    const int tkrow = (lane & 7) + ((lane >> 4) & 1) * 8;
    const int tncol = ((lane >> 3) & 1) * 8;
    const int lr = lane >> 2, lc = (lane & 3) * 2;

    if (tid < 64) { s_l[tid] = 0.f; s_y[tid] = 0.f; }

    // load U tile [64c][256kf] -> smem (cp.async)
    for (int i = tid; i < 2048; i += 256) {
        int row = i >> 5, c16 = i & 31;
        const void* src = g_Ubf + (size_t)(c0 + row) * KF + c16 * 8;
        CPA(aU + (row * USTR + c16 * 8) * 2, src, 16u);
    }

    auto load_xf = [&](int ch, int buf) {
        const uint32_t aX = aX0 + buf * XF_BYTES;
        #pragma unroll
        for (int it = 0; it < 16; it++) {
            int i = tid + it * 256;
            int row = i >> 5, c16 = i & 31;
            const void* src = g_xf + ((size_t)b * SSL + ch * 128 + row) * KF + c16 * 8;
            CPA(aX + (row * XSTR + c16 * 8) * 2, src, 16u);
        }
    };

    float macc[2][8][4] = {};      // m accumulator: 32c x 64k per warp
    float lacc[2][2] = {};         // l partials: rows (mt, h)

    const int NCH = SSL / 128;     // 16
    load_xf(0, 0); CP_COMMIT();
    for (int ch = 0; ch < NCH; ch++) {
        const uint32_t aX = aX0 + (ch & 1) * XF_BYTES;
        if (ch + 1 < NCH) { load_xf(ch + 1, (ch + 1) & 1); CP_COMMIT(); CP_WAIT1(); }
        else CP_WAIT0();
        __syncthreads();

        // ---- phase 1: S = U @ xf^T  (32c x 32s per warp) ----
        float acc1[2][4][4] = {};
        #pragma unroll
        for (int ks = 0; ks < 16; ks++) {
            uint32_t a[2][4];
            #pragma unroll
            for (int mt = 0; mt < 2; mt++)
                ldsm_x4(a[mt][0], a[mt][1], a[mt][2], a[mt][3],
                        aU + ((wcm + mt * 16 + lrow) * USTR + ks * 16 + lcol) * 2);
            #pragma unroll
            for (int nt = 0; nt < 2; nt++) {
                uint32_t b0, b1, b2, b3;
                ldsm_x4(b0, b1, b2, b3,
                        aX + ((wsn + nt * 16 + lrow) * XSTR + ks * 16 + lcol) * 2);
                #pragma unroll
                for (int mt = 0; mt < 2; mt++) {
                    mma_bf16(acc1[mt][nt * 2 + 0], a[mt][0], a[mt][1], a[mt][2], a[mt][3], b0, b2);
                    mma_bf16(acc1[mt][nt * 2 + 1], a[mt][0], a[mt][1], a[mt][2], a[mt][3], b1, b3);
                }
            }
        }
        // exp -> bf16 alpha smem; accumulate l partials (of bf16-rounded values)
        #pragma unroll
        for (int mt = 0; mt < 2; mt++)
            #pragma unroll
            for (int j = 0; j < 4; j++)
                #pragma unroll
                for (int h = 0; h < 2; h++) {
                    float e0 = fast_exp(acc1[mt][j][h * 2 + 0]);
                    float e1 = fast_exp(acc1[mt][j][h * 2 + 1]);
                    __nv_bfloat16 b0 = __float2bfloat16(e0);
                    __nv_bfloat16 b1 = __float2bfloat16(e1);
                    lacc[mt][h] += __bfloat162float(b0) + __bfloat162float(b1);
                    __nv_bfloat162 hh; hh.x = b0; hh.y = b1;
                    int c_loc = wcm + mt * 16 + lr + h * 8;
                    int s_loc = wsn + j * 8 + lc;
                    *reinterpret_cast<uint32_t*>(dsm + (aAL - aU) + (c_loc * ALSTR + s_loc) * 2)
                        = *(uint32_t*)&hh;
                }
        __syncthreads();

        // ---- phase 2: macc += alpha @ xf  (32c x 64k per warp, contraction s=128) ----
        #pragma unroll
        for (int ks = 0; ks < 8; ks++) {
            uint32_t a[2][4];
            #pragma unroll
            for (int mt = 0; mt < 2; mt++)
                ldsm_x4(a[mt][0], a[mt][1], a[mt][2], a[mt][3],
                        aAL + ((wcm + mt * 16 + lrow) * ALSTR + ks * 16 + lcol) * 2);
            #pragma unroll
            for (int nt = 0; nt < 4; nt++) {
                uint32_t b0, b1, b2, b3;
                ldsm_x4_t(b0, b1, b2, b3,
                          aX + ((ks * 16 + tkrow) * XSTR + wkn + nt * 16 + tncol) * 2);
                #pragma unroll
                for (int mt = 0; mt < 2; mt++) {
                    mma_bf16(macc[mt][nt * 2 + 0], a[mt][0], a[mt][1], a[mt][2], a[mt][3], b0, b2);
                    mma_bf16(macc[mt][nt * 2 + 1], a[mt][0], a[mt][1], a[mt][2], a[mt][3], b1, b3);
                }
            }
        }
        __syncthreads();   // protect alpha tile before next phase-1 writes
    }

    // ---- reduce l: quad shuffles -> smem ----
    #pragma unroll
    for (int mt = 0; mt < 2; mt++)
        #pragma unroll
        for (int h = 0; h < 2; h++) {
            float v = lacc[mt][h];
            v += __shfl_xor_sync(0xffffffffu, v, 1);
            v += __shfl_xor_sync(0xffffffffu, v, 2);
            if ((lane & 3) == 0)
                atomicAdd(&s_l[wcm + mt * 16 + lr + h * 8], v);
        }
    __syncthreads();

    // ---- epilogue: y = sum_k fw * m / l ----
    #pragma unroll
    for (int mt = 0; mt < 2; mt++)
        #pragma unroll
        for (int h = 0; h < 2; h++) {
            int c_loc = wcm + mt * 16 + lr + h * 8;
            float rl = 1.f / s_l[c_loc];
            const float* fwr = fw + (size_t)(c0 + c_loc) * KF + wkn;
            float yp = 0.f;
            #pragma unroll
            for (int j = 0; j < 8; j++) {
                int kc = j * 8 + lc;
                float2 w2 = *reinterpret_cast<const float2*>(fwr + kc);
                yp += w2.x * (macc[mt][j][h * 2 + 0] * rl);
                yp += w2.y * (macc[mt][j][h * 2 + 1] * rl);
            }
            yp += __shfl_xor_sync(0xffffffffu, yp, 1);
            yp += __shfl_xor_sync(0xffffffffu, yp, 2);
            if ((lane & 3) == 0) atomicAdd(&s_y[c_loc], yp);
        }
    __syncthreads();
    if (tid < 64)
        out[(size_t)b * CC + c0 + tid] = s_y[tid] + fb[c0 + tid];
}

// ---------------------------------------------------------------------------
extern "C" void kernel_launch(void* const* d_in, const int* in_sizes, int n_in,
                              void* d_out, int out_size) {
    const int*   text  = (const int*)  d_in[0];
    const float* table = (const float*)d_in[1];
    const float* convw = (const float*)d_in[2];
    const float* convb = (const float*)d_in[3];
    const float* Uw    = (const float*)d_in[4];
    const float* fw    = (const float*)d_in[5];
    const float* fb    = (const float*)d_in[6];
    float* out = (float*)d_out;

    const int SM_CONV = 3 * (CONV_A_STG + CONV_B_STG);   // 78720
    static int attr_done = 0;
    if (!attr_done) {
        cudaFuncSetAttribute(k_conv_mma, cudaFuncAttributeMaxDynamicSharedMemorySize, SM_CONV);
        cudaFuncSetAttribute(k_fused,    cudaFuncAttributeMaxDynamicSharedMemorySize, SM_FUSED);
        attr_done = 1;
    }

    k_gather<<<(BB*SSL*(DD/4) + 255) / 256, 256>>>(text, table);
    k_wprep <<<(JJ*KF*DD + 255) / 256, 256>>>(convw);
    k_uprep <<<(CC*KF + 255) / 256, 256>>>(Uw);
    k_conv_mma<<<dim3(SSL/128, KF/64, BB), 256, SM_CONV>>>(convb);
    k_fused   <<<dim3(CC/64, BB), 256, SM_FUSED>>>(fw, fb, out);
}